// round 13
// baseline (speedup 1.0000x reference)
#include <cuda_runtime.h>
#include <cuda_fp16.h>
#include <cstdint>

#define IN_DIM  1024
#define HID_DIM 4096
#define OUT_DIM 1024
#define N_EXP   8
#define BATCH   8192

// ---------------- scratch (device globals; no allocation) ----------------
__device__ int   g_counts[N_EXP];
__device__ int   g_offsets[N_EXP];
__device__ int   g_expert_of[BATCH];
__device__ int   g_rank[BATCH];                        // rank of token within its expert
__device__ int   g_perm[BATCH];                        // gathered row -> original token
__device__ int   g_conv_done[N_EXP + 1];               // blocks finished per region
__device__ volatile int g_wflag[N_EXP + 1];            // weights-region ready flags
__device__ __align__(16) __half g_xh[(size_t)BATCH * IN_DIM];            // x fp16, ORIGINAL order
__device__ __align__(16) __half g_hh[(size_t)BATCH * HID_DIM];           // hidden fp16, gathered order
__device__ __align__(16) __half g_ewh[(size_t)N_EXP * IN_DIM * HID_DIM]; // expert_w fp16 [e][k][n]
__device__ __align__(16) __half g_pwh[(size_t)HID_DIM * OUT_DIM];        // proj_w fp16 [k][n]

// ---------------- small kernels ----------------
__global__ void zero_kernel() {
    if (threadIdx.x < N_EXP) g_counts[threadIdx.x] = 0;
    if (threadIdx.x < N_EXP + 1) g_wflag[threadIdx.x] = 0;
}

// router: logits/argmax/one-hot, fp16 copy of x, and rank-within-expert
__global__ void router_kernel(const float* __restrict__ x,
                              const float* __restrict__ rw,
                              const float* __restrict__ rb,
                              float* __restrict__ route_out) {
    int warp = (blockIdx.x * blockDim.x + threadIdx.x) >> 5;
    int lane = threadIdx.x & 31;
    if (warp >= BATCH) return;
    const float2* xr = reinterpret_cast<const float2*>(x + (size_t)warp * IN_DIM);
    uint32_t* dst = reinterpret_cast<uint32_t*>(g_xh + (size_t)warp * IN_DIM);
    float acc[N_EXP];
#pragma unroll
    for (int e = 0; e < N_EXP; e++) acc[e] = 0.f;
#pragma unroll 4
    for (int i = 0; i < 16; i++) {
        int k2 = lane + 32 * i;                 // float2 index: floats 2*k2, 2*k2+1
        float2 v = xr[k2];
        const float4* w = reinterpret_cast<const float4*>(rw + (size_t)k2 * 2 * N_EXP);
        float4 w0 = w[0], w1 = w[1], w2 = w[2], w3 = w[3];
        acc[0] += v.x * w0.x + v.y * w2.x; acc[1] += v.x * w0.y + v.y * w2.y;
        acc[2] += v.x * w0.z + v.y * w2.z; acc[3] += v.x * w0.w + v.y * w2.w;
        acc[4] += v.x * w1.x + v.y * w3.x; acc[5] += v.x * w1.y + v.y * w3.y;
        acc[6] += v.x * w1.z + v.y * w3.z; acc[7] += v.x * w1.w + v.y * w3.w;
        __half2 h = __floats2half2_rn(v.x, v.y);
        dst[k2] = *reinterpret_cast<uint32_t*>(&h);
    }
#pragma unroll
    for (int e = 0; e < N_EXP; e++) {
#pragma unroll
        for (int off = 16; off > 0; off >>= 1)
            acc[e] += __shfl_down_sync(0xffffffffu, acc[e], off);
    }
    if (lane == 0) {
        float best = acc[0] + rb[0]; int bi = 0;
#pragma unroll
        for (int e = 1; e < N_EXP; e++) {
            float v = acc[e] + rb[e];
            if (v > best) { best = v; bi = e; }   // first-max wins == jnp.argmax
        }
        g_expert_of[warp] = bi;
        g_rank[warp] = atomicAdd(&g_counts[bi], 1);   // rank within expert
        float* ro = route_out + (size_t)warp * N_EXP;
#pragma unroll
        for (int e = 0; e < N_EXP; e++) ro[e] = (e == bi) ? 1.f : 0.f;
    }
}

// fused scan (redundant per block, N_EXP=8 is tiny) + perm write, no atomics
__global__ void perm_kernel() {
    __shared__ int offs[N_EXP];
    if (threadIdx.x == 0) {
        int s = 0;
#pragma unroll
        for (int e = 0; e < N_EXP; e++) {
            offs[e] = s;
            if (blockIdx.x == 0) g_offsets[e] = s;
            s += g_counts[e];
        }
    }
    __syncthreads();
    int i = blockIdx.x * blockDim.x + threadIdx.x;
    if (i < BATCH) {
        int e = g_expert_of[i];
        g_perm[offs[e] + g_rank[i]] = i;
    }
}

// fp32 -> fp16 weight conversion, statically partitioned:
// region r in [0,8): expert r of expert_w; region 8: proj_w.
// 256 blocks per region; last block of a region raises its ready flag.
constexpr int CONV_BPR = 256;                                   // blocks per region
constexpr int CONV_CHUNK = (IN_DIM * HID_DIM / 4) / CONV_BPR;   // 4096 float4 per block
static_assert((HID_DIM * OUT_DIM / 4) / CONV_BPR == CONV_CHUNK, "chunk mismatch");

__global__ void convert_kernel(const float4* __restrict__ ew,
                               const float4* __restrict__ pw) {
    int region = blockIdx.x >> 8;          // 0..8
    int rb     = blockIdx.x & 255;
    size_t base = (size_t)rb * CONV_CHUNK;
    const float4* src;
    uint2* dst;
    if (region < N_EXP) {
        size_t ebase = (size_t)region * (IN_DIM * HID_DIM / 4) + base;
        src = ew + ebase;
        dst = reinterpret_cast<uint2*>(g_ewh) + ebase;
    } else {
        src = pw + base;
        dst = reinterpret_cast<uint2*>(g_pwh) + base;
    }
    for (int i = threadIdx.x; i < CONV_CHUNK; i += blockDim.x) {
        float4 v = src[i];
        __half2 h0 = __floats2half2_rn(v.x, v.y);
        __half2 h1 = __floats2half2_rn(v.z, v.w);
        uint2 u;
        u.x = *reinterpret_cast<uint32_t*>(&h0);
        u.y = *reinterpret_cast<uint32_t*>(&h1);
        dst[i] = u;
    }
    __syncthreads();
    __threadfence();
    if (threadIdx.x == 0) {
        if (atomicAdd(&g_conv_done[region], 1) == CONV_BPR - 1) {
            g_conv_done[region] = 0;       // reset for next graph replay
            g_wflag[region] = 1;           // publish: region weights ready
        }
    }
}

// ---------------- fp16 mma.sync GEMM (128x128x32, 256 threads, 3-stage) ----------------
constexpr int BM = 128, BN = 128, BK = 32, THREADS = 256, STAGES = 3;
constexpr int ASTRIDE = 80;                     // bytes/row: 32 halves + 8 pad
constexpr int BSTRIDE = 272;                    // bytes/row: 128 halves + 8 pad
constexpr int A_BYTES = BM * ASTRIDE;           // 10240
constexpr int B_BYTES = BK * BSTRIDE;           // 8704
constexpr int STAGE_BYTES = A_BYTES + B_BYTES;  // 18944
constexpr int PERM_OFF = STAGES * STAGE_BYTES;  // 56832
constexpr int GEMM_SMEM = PERM_OFF + BM * 4;    // 57344

__device__ __forceinline__ void cp_async16(uint32_t sm, const void* g, bool p) {
    int bytes = p ? 16 : 0;
    asm volatile("cp.async.cg.shared.global [%0], [%1], 16, %2;\n"
                 :: "r"(sm), "l"(g), "r"(bytes));
}
__device__ __forceinline__ void cp_commit() { asm volatile("cp.async.commit_group;\n"); }
template <int N> __device__ __forceinline__ void cp_wait() {
    asm volatile("cp.async.wait_group %0;\n" :: "n"(N));
}
__device__ __forceinline__ void ldsm_x4(uint32_t* r, uint32_t addr) {
    asm volatile("ldmatrix.sync.aligned.m8n8.x4.shared.b16 {%0,%1,%2,%3}, [%4];\n"
                 : "=r"(r[0]), "=r"(r[1]), "=r"(r[2]), "=r"(r[3]) : "r"(addr));
}
__device__ __forceinline__ void ldsm_x4_t(uint32_t* r, uint32_t addr) {
    asm volatile("ldmatrix.sync.aligned.m8n8.x4.trans.shared.b16 {%0,%1,%2,%3}, [%4];\n"
                 : "=r"(r[0]), "=r"(r[1]), "=r"(r[2]), "=r"(r[3]) : "r"(addr));
}
__device__ __forceinline__ void mma_f16(float* c, const uint32_t* a,
                                        uint32_t b0, uint32_t b1) {
    asm volatile(
        "mma.sync.aligned.m16n8k16.row.col.f32.f16.f16.f32 "
        "{%0,%1,%2,%3}, {%4,%5,%6,%7}, {%8,%9}, {%0,%1,%2,%3};\n"
        : "+f"(c[0]), "+f"(c[1]), "+f"(c[2]), "+f"(c[3])
        : "r"(a[0]), "r"(a[1]), "r"(a[2]), "r"(a[3]), "r"(b0), "r"(b1));
}

// EXPERT: one 128x128 tile per CTA (ragged M, A rows indirect via perm),
//         spin-waits on its expert's weight-ready flag (convert overlaps).
// !EXPERT: persistent CTAs looping over all (m,n) tiles of the proj GEMM.
template <bool EXPERT>
__global__ __launch_bounds__(THREADS, 2)
void gemm_f16_kernel(const float* __restrict__ biasGlob,
                     float* __restrict__ outGlob) {
    constexpr int Ksz = EXPERT ? IN_DIM : HID_DIM;
    constexpr int Nsz = EXPERT ? HID_DIM : OUT_DIM;
    constexpr int KT = Ksz / BK;
    constexpr int NTILES = EXPERT ? 1 : (BATCH / BM) * (OUT_DIM / BN);  // 512

    extern __shared__ char smem[];
    uint32_t sm;
    asm("{ .reg .u64 t; cvta.to.shared.u64 t, %1; cvt.u32.u64 %0, t; }"
        : "=r"(sm) : "l"(smem));
    int* sperm = reinterpret_cast<int*>(smem + PERM_OFF);
    int tid = threadIdx.x;
    int lane = tid & 31, warp = tid >> 5;
    int wm = warp & 1, wn = warp >> 1;           // 2 warps (M=64) x 4 warps (N=32)
    uint32_t a_loff = (uint32_t)((lane & 15) * ASTRIDE + ((lane >> 4) & 1) * 16);
    uint32_t b_loff = (uint32_t)(((lane & 7) + ((lane >> 3) & 1) * 8) * BSTRIDE +
                                 ((lane >> 4) & 1) * 16);
    int g = lane >> 2, t4 = lane & 3;

    int M = BATCH, arow0 = 0;
    const __half* B = g_pwh;
    const float* bias = biasGlob;
    __half* hC = nullptr;
    if constexpr (EXPERT) {
        int e = blockIdx.z;
        M    = g_counts[e];
        B    = g_ewh + (size_t)e * IN_DIM * HID_DIM;
        bias = biasGlob + (size_t)e * HID_DIM;
        hC   = g_hh + (size_t)g_offsets[e] * HID_DIM;
        int mb = blockIdx.y * BM;
        if (mb >= M) return;
        arow0 = mb;
        // cache this tile's perm slice (gathered row -> original token)
        if (tid < BM) {
            int gi = g_offsets[e] + mb + tid;
            sperm[tid] = g_perm[gi < BATCH ? gi : BATCH - 1];
        }
        // wait until this expert's fp16 weights are published by convert_kernel
        if (tid == 0) {
            while (g_wflag[e] == 0) { }
            __threadfence();
        }
    }

    for (int tile = EXPERT ? 0 : blockIdx.x; tile < NTILES;
         tile += EXPERT ? NTILES : gridDim.x) {
        int m_blk, n_blk;
        if constexpr (EXPERT) { m_blk = arow0; n_blk = blockIdx.x * BN; }
        else                  { m_blk = (tile >> 3) * BM; n_blk = (tile & 7) * BN; }
        __syncthreads();   // perm slice + weight flag visible / smem stages safe to reuse

        auto load_tiles = [&](int kt, int s) {
            uint32_t sa = sm + s * STAGE_BYTES;
#pragma unroll
            for (int n = 0; n < 2; n++) {          // A: 128 rows x 4 chunks
                int id = tid + n * THREADS;
                int r = id >> 2, c = id & 3;
                bool ok = (m_blk + r) < M;
                const __half* src;
                if constexpr (EXPERT)
                    src = g_xh + (size_t)sperm[r] * IN_DIM + kt * BK + c * 8;
                else
                    src = g_hh + (size_t)(ok ? m_blk + r : 0) * Ksz + kt * BK + c * 8;
                cp_async16(sa + r * ASTRIDE + c * 16, src, ok);
            }
            uint32_t sb = sa + A_BYTES;
#pragma unroll
            for (int n = 0; n < 2; n++) {          // B: 32 rows x 16 chunks
                int id = tid + n * THREADS;
                int r = id >> 4, c = id & 15;
                const __half* src = B + (size_t)(kt * BK + r) * Nsz + n_blk + c * 8;
                cp_async16(sb + r * BSTRIDE + c * 16, src, true);
            }
            cp_commit();
        };

        float acc[4][4][4];
#pragma unroll
        for (int i = 0; i < 4; i++)
#pragma unroll
            for (int j = 0; j < 4; j++)
#pragma unroll
                for (int q = 0; q < 4; q++) acc[i][j][q] = 0.f;

        load_tiles(0, 0);
        load_tiles(1, 1);
        for (int kt = 0; kt < KT; kt++) {
            if (kt + 1 < KT) cp_wait<1>(); else cp_wait<0>();
            __syncthreads();
            if (kt + 2 < KT) load_tiles(kt + 2, (kt + 2) % STAGES);
            uint32_t sa = sm + (kt % STAGES) * STAGE_BYTES;
            uint32_t sb = sa + A_BYTES;
#pragma unroll
            for (int ks = 0; ks < 2; ks++) {
                uint32_t af[4][4], bf[2][4];
#pragma unroll
                for (int i = 0; i < 4; i++)
                    ldsm_x4(af[i], sa + a_loff + (wm * 64 + i * 16) * ASTRIDE + ks * 32);
#pragma unroll
                for (int j = 0; j < 2; j++)
                    ldsm_x4_t(bf[j], sb + b_loff + ks * 16 * BSTRIDE + (wn * 32 + j * 16) * 2);
#pragma unroll
                for (int i = 0; i < 4; i++) {
                    mma_f16(acc[i][0], af[i], bf[0][0], bf[0][1]);
                    mma_f16(acc[i][1], af[i], bf[0][2], bf[0][3]);
                    mma_f16(acc[i][2], af[i], bf[1][0], bf[1][1]);
                    mma_f16(acc[i][3], af[i], bf[1][2], bf[1][3]);
                }
            }
        }

        // epilogue
#pragma unroll
        for (int i = 0; i < 4; i++) {
            int r0 = m_blk + wm * 64 + i * 16 + g;
            int r1 = r0 + 8;
#pragma unroll
            for (int j = 0; j < 4; j++) {
                int c = n_blk + wn * 32 + j * 8 + 2 * t4;
                float bv0 = bias[c], bv1 = bias[c + 1];
                float v00 = acc[i][j][0] + bv0;
                float v01 = acc[i][j][1] + bv1;
                float v10 = acc[i][j][2] + bv0;
                float v11 = acc[i][j][3] + bv1;
                if constexpr (EXPERT) {
                    if (r0 < M) {
                        __half2 h = __floats2half2_rn(v00, v01);
                        *reinterpret_cast<uint32_t*>(hC + (size_t)r0 * HID_DIM + c) =
                            *reinterpret_cast<uint32_t*>(&h);
                    }
                    if (r1 < M) {
                        __half2 h = __floats2half2_rn(v10, v11);
                        *reinterpret_cast<uint32_t*>(hC + (size_t)r1 * HID_DIM + c) =
                            *reinterpret_cast<uint32_t*>(&h);
                    }
                } else {
                    int o0 = g_perm[r0], o1 = g_perm[r1];   // scatter rows back
                    float2* p0 = reinterpret_cast<float2*>(outGlob + (size_t)o0 * OUT_DIM + c);
                    float2* p1 = reinterpret_cast<float2*>(outGlob + (size_t)o1 * OUT_DIM + c);
                    *p0 = make_float2(v00, v01);
                    *p1 = make_float2(v10, v11);
                }
            }
        }
    }
}

// ---------------- launch ----------------
extern "C" void kernel_launch(void* const* d_in, const int* in_sizes, int n_in,
                              void* d_out, int out_size) {
    const float* x        = (const float*)d_in[0];
    const float* router_w = (const float*)d_in[1];
    const float* router_b = (const float*)d_in[2];
    const float* expert_w = (const float*)d_in[3];
    const float* expert_b = (const float*)d_in[4];
    const float* proj_w   = (const float*)d_in[5];
    const float* proj_b   = (const float*)d_in[6];

    float* out       = (float*)d_out;
    float* route_out = out + (size_t)BATCH * OUT_DIM;   // [out | one_hot]

    // one-time setup on the FIRST (uncaptured correctness) call; reused during capture
    static cudaStream_t s2 = nullptr;
    static cudaEvent_t ev_fork = nullptr, ev_join = nullptr;
    if (!s2) {
        cudaStreamCreateWithFlags(&s2, cudaStreamNonBlocking);
        cudaEventCreateWithFlags(&ev_fork, cudaEventDisableTiming);
        cudaEventCreateWithFlags(&ev_join, cudaEventDisableTiming);
        cudaFuncSetAttribute(gemm_f16_kernel<true>,
                             cudaFuncAttributeMaxDynamicSharedMemorySize, GEMM_SMEM);
        cudaFuncSetAttribute(gemm_f16_kernel<false>,
                             cudaFuncAttributeMaxDynamicSharedMemorySize, GEMM_SMEM);
    }

    // flags/counters must be reset BEFORE convert runs (each replay)
    zero_kernel<<<1, 32>>>();

    // fork: weight conversion runs concurrently; GEMM1 synchronizes per-expert
    // via device flags, so it does NOT need an event join.
    cudaEventRecord(ev_fork, 0);
    cudaStreamWaitEvent(s2, ev_fork, 0);
    convert_kernel<<<(N_EXP + 1) * CONV_BPR, 256, 0, s2>>>(
        (const float4*)expert_w, (const float4*)proj_w);
    cudaEventRecord(ev_join, s2);

    router_kernel<<<BATCH / 8, 256>>>(x, router_w, router_b, route_out);
    perm_kernel<<<BATCH / 256, 256>>>();

    gemm_f16_kernel<true><<<dim3(HID_DIM / BN, BATCH / BM, N_EXP),
                            THREADS, GEMM_SMEM>>>(expert_b, nullptr);

    // proj GEMM needs proj_w converted; convert is long finished, join is free
    cudaStreamWaitEvent(0, ev_join, 0);
    gemm_f16_kernel<false><<<dim3(296, 1, 1),
                             THREADS, GEMM_SMEM>>>(proj_b, out);
}

// round 14
// speedup vs baseline: 1.0343x; 1.0343x over previous
#include <cuda_runtime.h>
#include <cuda_fp16.h>
#include <cstdint>

#define IN_DIM  1024
#define HID_DIM 4096
#define OUT_DIM 1024
#define N_EXP   8
#define BATCH   8192

// ---------------- scratch (device globals; no allocation) ----------------
__device__ int   g_counts[N_EXP];
__device__ int   g_offsets[N_EXP];
__device__ int   g_expert_of[BATCH];
__device__ int   g_rank[BATCH];                        // rank of token within its expert
__device__ int   g_perm[BATCH];                        // gathered row -> original token
__device__ __align__(16) __half g_xh[(size_t)BATCH * IN_DIM];            // x fp16, ORIGINAL order
__device__ __align__(16) __half g_hh[(size_t)BATCH * HID_DIM];           // hidden fp16, gathered order
__device__ __align__(16) __half g_ewh[(size_t)N_EXP * IN_DIM * HID_DIM]; // expert_w fp16 [e][k][n]
__device__ __align__(16) __half g_pwh[(size_t)HID_DIM * OUT_DIM];        // proj_w fp16 [k][n]

// ---------------- small kernels ----------------
__global__ void zero_kernel() {
    if (threadIdx.x < N_EXP) g_counts[threadIdx.x] = 0;
}

// zero the out region of d_out (split-K accumulates into it with atomics)
__global__ void zero_out_kernel(float4* __restrict__ out4) {
    const size_t N4 = (size_t)BATCH * OUT_DIM / 4;
    size_t stride = (size_t)gridDim.x * blockDim.x;
    for (size_t i = (size_t)blockIdx.x * blockDim.x + threadIdx.x; i < N4; i += stride)
        out4[i] = make_float4(0.f, 0.f, 0.f, 0.f);
}

// router: logits/argmax/one-hot, fp16 copy of x, and rank-within-expert
__global__ void router_kernel(const float* __restrict__ x,
                              const float* __restrict__ rw,
                              const float* __restrict__ rb,
                              float* __restrict__ route_out) {
    int warp = (blockIdx.x * blockDim.x + threadIdx.x) >> 5;
    int lane = threadIdx.x & 31;
    if (warp >= BATCH) return;
    const float2* xr = reinterpret_cast<const float2*>(x + (size_t)warp * IN_DIM);
    uint32_t* dst = reinterpret_cast<uint32_t*>(g_xh + (size_t)warp * IN_DIM);
    float acc[N_EXP];
#pragma unroll
    for (int e = 0; e < N_EXP; e++) acc[e] = 0.f;
#pragma unroll 4
    for (int i = 0; i < 16; i++) {
        int k2 = lane + 32 * i;                 // float2 index: floats 2*k2, 2*k2+1
        float2 v = xr[k2];
        const float4* w = reinterpret_cast<const float4*>(rw + (size_t)k2 * 2 * N_EXP);
        float4 w0 = w[0], w1 = w[1], w2 = w[2], w3 = w[3];
        acc[0] += v.x * w0.x + v.y * w2.x; acc[1] += v.x * w0.y + v.y * w2.y;
        acc[2] += v.x * w0.z + v.y * w2.z; acc[3] += v.x * w0.w + v.y * w2.w;
        acc[4] += v.x * w1.x + v.y * w3.x; acc[5] += v.x * w1.y + v.y * w3.y;
        acc[6] += v.x * w1.z + v.y * w3.z; acc[7] += v.x * w1.w + v.y * w3.w;
        __half2 h = __floats2half2_rn(v.x, v.y);
        dst[k2] = *reinterpret_cast<uint32_t*>(&h);
    }
#pragma unroll
    for (int e = 0; e < N_EXP; e++) {
#pragma unroll
        for (int off = 16; off > 0; off >>= 1)
            acc[e] += __shfl_down_sync(0xffffffffu, acc[e], off);
    }
    if (lane == 0) {
        float best = acc[0] + rb[0]; int bi = 0;
#pragma unroll
        for (int e = 1; e < N_EXP; e++) {
            float v = acc[e] + rb[e];
            if (v > best) { best = v; bi = e; }   // first-max wins == jnp.argmax
        }
        g_expert_of[warp] = bi;
        g_rank[warp] = atomicAdd(&g_counts[bi], 1);   // rank within expert
        float* ro = route_out + (size_t)warp * N_EXP;
#pragma unroll
        for (int e = 0; e < N_EXP; e++) ro[e] = (e == bi) ? 1.f : 0.f;
    }
}

// fused scan (redundant per block, N_EXP=8 is tiny) + perm write, no atomics
__global__ void perm_kernel() {
    __shared__ int offs[N_EXP];
    if (threadIdx.x == 0) {
        int s = 0;
#pragma unroll
        for (int e = 0; e < N_EXP; e++) {
            offs[e] = s;
            if (blockIdx.x == 0) g_offsets[e] = s;
            s += g_counts[e];
        }
    }
    __syncthreads();
    int i = blockIdx.x * blockDim.x + threadIdx.x;
    if (i < BATCH) {
        int e = g_expert_of[i];
        g_perm[offs[e] + g_rank[i]] = i;
    }
}

// fp32 -> fp16 conversion: expert_w part (joined before GEMM1)
__global__ void convert_expert_kernel(const float4* __restrict__ ew) {
    const size_t N4 = (size_t)N_EXP * IN_DIM * HID_DIM / 4;
    size_t stride = (size_t)gridDim.x * blockDim.x;
    uint2* dst = reinterpret_cast<uint2*>(g_ewh);
    for (size_t i = (size_t)blockIdx.x * blockDim.x + threadIdx.x; i < N4; i += stride) {
        float4 v = ew[i];
        __half2 h0 = __floats2half2_rn(v.x, v.y);
        __half2 h1 = __floats2half2_rn(v.z, v.w);
        uint2 u;
        u.x = *reinterpret_cast<uint32_t*>(&h0);
        u.y = *reinterpret_cast<uint32_t*>(&h1);
        dst[i] = u;
    }
}

// fp32 -> fp16 conversion: proj_w part (joined before GEMM2)
__global__ void convert_proj_kernel(const float4* __restrict__ pw) {
    const size_t N4 = (size_t)HID_DIM * OUT_DIM / 4;
    size_t stride = (size_t)gridDim.x * blockDim.x;
    uint2* dst = reinterpret_cast<uint2*>(g_pwh);
    for (size_t i = (size_t)blockIdx.x * blockDim.x + threadIdx.x; i < N4; i += stride) {
        float4 v = pw[i];
        __half2 h0 = __floats2half2_rn(v.x, v.y);
        __half2 h1 = __floats2half2_rn(v.z, v.w);
        uint2 u;
        u.x = *reinterpret_cast<uint32_t*>(&h0);
        u.y = *reinterpret_cast<uint32_t*>(&h1);
        dst[i] = u;
    }
}

// ---------------- fp16 mma.sync GEMM building blocks ----------------
constexpr int BM = 128, BN = 128, BK = 32, THREADS = 256, STAGES = 3;
constexpr int ASTRIDE = 80;                     // bytes/row: 32 halves + 8 pad
constexpr int BSTRIDE = 272;                    // bytes/row: 128 halves + 8 pad
constexpr int A_BYTES = BM * ASTRIDE;           // 10240
constexpr int B_BYTES = BK * BSTRIDE;           // 8704
constexpr int STAGE_BYTES = A_BYTES + B_BYTES;  // 18944
constexpr int PERM_OFF = STAGES * STAGE_BYTES;  // 56832
constexpr int GEMM_SMEM = PERM_OFF + BM * 4;    // 57344 (gemm1: +perm slice)
constexpr int GEMM2_SMEM = STAGES * STAGE_BYTES; // 56832

__device__ __forceinline__ void cp_async16(uint32_t sm, const void* g, bool p) {
    int bytes = p ? 16 : 0;
    asm volatile("cp.async.cg.shared.global [%0], [%1], 16, %2;\n"
                 :: "r"(sm), "l"(g), "r"(bytes));
}
__device__ __forceinline__ void cp_commit() { asm volatile("cp.async.commit_group;\n"); }
template <int N> __device__ __forceinline__ void cp_wait() {
    asm volatile("cp.async.wait_group %0;\n" :: "n"(N));
}
__device__ __forceinline__ void ldsm_x4(uint32_t* r, uint32_t addr) {
    asm volatile("ldmatrix.sync.aligned.m8n8.x4.shared.b16 {%0,%1,%2,%3}, [%4];\n"
                 : "=r"(r[0]), "=r"(r[1]), "=r"(r[2]), "=r"(r[3]) : "r"(addr));
}
__device__ __forceinline__ void ldsm_x4_t(uint32_t* r, uint32_t addr) {
    asm volatile("ldmatrix.sync.aligned.m8n8.x4.trans.shared.b16 {%0,%1,%2,%3}, [%4];\n"
                 : "=r"(r[0]), "=r"(r[1]), "=r"(r[2]), "=r"(r[3]) : "r"(addr));
}
__device__ __forceinline__ void mma_f16(float* c, const uint32_t* a,
                                        uint32_t b0, uint32_t b1) {
    asm volatile(
        "mma.sync.aligned.m16n8k16.row.col.f32.f16.f16.f32 "
        "{%0,%1,%2,%3}, {%4,%5,%6,%7}, {%8,%9}, {%0,%1,%2,%3};\n"
        : "+f"(c[0]), "+f"(c[1]), "+f"(c[2]), "+f"(c[3])
        : "r"(a[0]), "r"(a[1]), "r"(a[2]), "r"(a[3]), "r"(b0), "r"(b1));
}

// ---------------- GEMM1: expert GEMM (ragged M, perm-indirect A) ----------------
__global__ __launch_bounds__(THREADS, 2)
void gemm1_kernel(const float* __restrict__ biasGlob) {
    constexpr int KT = IN_DIM / BK;     // 32

    extern __shared__ char smem[];
    uint32_t sm;
    asm("{ .reg .u64 t; cvta.to.shared.u64 t, %1; cvt.u32.u64 %0, t; }"
        : "=r"(sm) : "l"(smem));
    int* sperm = reinterpret_cast<int*>(smem + PERM_OFF);
    int tid = threadIdx.x;
    int lane = tid & 31, warp = tid >> 5;
    int wm = warp & 1, wn = warp >> 1;           // 2 warps (M=64) x 4 warps (N=32)
    uint32_t a_loff = (uint32_t)((lane & 15) * ASTRIDE + ((lane >> 4) & 1) * 16);
    uint32_t b_loff = (uint32_t)(((lane & 7) + ((lane >> 3) & 1) * 8) * BSTRIDE +
                                 ((lane >> 4) & 1) * 16);
    int g = lane >> 2, t4 = lane & 3;

    int e = blockIdx.z;
    int M = g_counts[e];
    int m_blk = blockIdx.y * BM;
    if (m_blk >= M) return;
    int n_blk = blockIdx.x * BN;
    const __half* B = g_ewh + (size_t)e * IN_DIM * HID_DIM;
    const float* bias = biasGlob + (size_t)e * HID_DIM;
    __half* hC = g_hh + (size_t)g_offsets[e] * HID_DIM;

    if (tid < BM) {
        int gi = g_offsets[e] + m_blk + tid;
        sperm[tid] = g_perm[gi < BATCH ? gi : BATCH - 1];
    }
    __syncthreads();

    auto load_tiles = [&](int kt, int s) {
        uint32_t sa = sm + s * STAGE_BYTES;
#pragma unroll
        for (int n = 0; n < 2; n++) {          // A: 128 rows x 4 chunks
            int id = tid + n * THREADS;
            int r = id >> 2, c = id & 3;
            bool ok = (m_blk + r) < M;
            const __half* src = g_xh + (size_t)sperm[r] * IN_DIM + kt * BK + c * 8;
            cp_async16(sa + r * ASTRIDE + c * 16, src, ok);
        }
        uint32_t sb = sa + A_BYTES;
#pragma unroll
        for (int n = 0; n < 2; n++) {          // B: 32 rows x 16 chunks
            int id = tid + n * THREADS;
            int r = id >> 4, c = id & 15;
            const __half* src = B + (size_t)(kt * BK + r) * HID_DIM + n_blk + c * 8;
            cp_async16(sb + r * BSTRIDE + c * 16, src, true);
        }
        cp_commit();
    };

    float acc[4][4][4];
#pragma unroll
    for (int i = 0; i < 4; i++)
#pragma unroll
        for (int j = 0; j < 4; j++)
#pragma unroll
            for (int q = 0; q < 4; q++) acc[i][j][q] = 0.f;

    load_tiles(0, 0);
    load_tiles(1, 1);
    for (int kt = 0; kt < KT; kt++) {
        if (kt + 1 < KT) cp_wait<1>(); else cp_wait<0>();
        __syncthreads();
        if (kt + 2 < KT) load_tiles(kt + 2, (kt + 2) % STAGES);
        uint32_t sa = sm + (kt % STAGES) * STAGE_BYTES;
        uint32_t sb = sa + A_BYTES;
#pragma unroll
        for (int ks = 0; ks < 2; ks++) {
            uint32_t af[4][4], bf[2][4];
#pragma unroll
            for (int i = 0; i < 4; i++)
                ldsm_x4(af[i], sa + a_loff + (wm * 64 + i * 16) * ASTRIDE + ks * 32);
#pragma unroll
            for (int j = 0; j < 2; j++)
                ldsm_x4_t(bf[j], sb + b_loff + ks * 16 * BSTRIDE + (wn * 32 + j * 16) * 2);
#pragma unroll
            for (int i = 0; i < 4; i++) {
                mma_f16(acc[i][0], af[i], bf[0][0], bf[0][1]);
                mma_f16(acc[i][1], af[i], bf[0][2], bf[0][3]);
                mma_f16(acc[i][2], af[i], bf[1][0], bf[1][1]);
                mma_f16(acc[i][3], af[i], bf[1][2], bf[1][3]);
            }
        }
    }

    // epilogue -> g_hh (fp16)
#pragma unroll
    for (int i = 0; i < 4; i++) {
        int r0 = m_blk + wm * 64 + i * 16 + g;
        int r1 = r0 + 8;
#pragma unroll
        for (int j = 0; j < 4; j++) {
            int c = n_blk + wn * 32 + j * 8 + 2 * t4;
            float bv0 = bias[c], bv1 = bias[c + 1];
            if (r0 < M) {
                __half2 h = __floats2half2_rn(acc[i][j][0] + bv0, acc[i][j][1] + bv1);
                *reinterpret_cast<uint32_t*>(hC + (size_t)r0 * HID_DIM + c) =
                    *reinterpret_cast<uint32_t*>(&h);
            }
            if (r1 < M) {
                __half2 h = __floats2half2_rn(acc[i][j][2] + bv0, acc[i][j][3] + bv1);
                *reinterpret_cast<uint32_t*>(hC + (size_t)r1 * HID_DIM + c) =
                    *reinterpret_cast<uint32_t*>(&h);
            }
        }
    }
}

// ---------------- GEMM2: proj GEMM with split-K=4 ----------------
// grid (8 n, 64 m, 4 kslice) = 2048 CTAs of K=1024 each -> 6.92 waves at
// 296 slots (vs 1.73 -> ceil 2 at split-K=1): wave-quantization waste ~1%.
// Partials accumulated into zero-initialized d_out via atomicAdd (fp32 adds
// of 4 values commute; result differs only in association ~1ulp).
constexpr int KSPLIT = 4;
constexpr int KT2 = (HID_DIM / BK) / KSPLIT;   // 32 k-tiles per slice

__global__ __launch_bounds__(THREADS, 2)
void gemm2_kernel(const float* __restrict__ bias,
                  float* __restrict__ outGlob) {
    extern __shared__ char smem[];
    uint32_t sm;
    asm("{ .reg .u64 t; cvta.to.shared.u64 t, %1; cvt.u32.u64 %0, t; }"
        : "=r"(sm) : "l"(smem));
    int tid = threadIdx.x;
    int lane = tid & 31, warp = tid >> 5;
    int wm = warp & 1, wn = warp >> 1;           // 2 warps (M=64) x 4 warps (N=32)
    uint32_t a_loff = (uint32_t)((lane & 15) * ASTRIDE + ((lane >> 4) & 1) * 16);
    uint32_t b_loff = (uint32_t)(((lane & 7) + ((lane >> 3) & 1) * 8) * BSTRIDE +
                                 ((lane >> 4) & 1) * 16);
    int g = lane >> 2, t4 = lane & 3;

    int m_blk = blockIdx.y * BM;
    int n_blk = blockIdx.x * BN;
    int k0 = blockIdx.z * KT2;                   // k-tile base of this slice

    auto load_tiles = [&](int kt, int s) {
        uint32_t sa = sm + s * STAGE_BYTES;
#pragma unroll
        for (int n = 0; n < 2; n++) {          // A: 128 rows x 4 chunks
            int id = tid + n * THREADS;
            int r = id >> 2, c = id & 3;
            const __half* src = g_hh + (size_t)(m_blk + r) * HID_DIM
                                + (k0 + kt) * BK + c * 8;
            cp_async16(sa + r * ASTRIDE + c * 16, src, true);
        }
        uint32_t sb = sa + A_BYTES;
#pragma unroll
        for (int n = 0; n < 2; n++) {          // B: 32 rows x 16 chunks
            int id = tid + n * THREADS;
            int r = id >> 4, c = id & 15;
            const __half* src = g_pwh + (size_t)((k0 + kt) * BK + r) * OUT_DIM
                                + n_blk + c * 8;
            cp_async16(sb + r * BSTRIDE + c * 16, src, true);
        }
        cp_commit();
    };

    float acc[4][4][4];
#pragma unroll
    for (int i = 0; i < 4; i++)
#pragma unroll
        for (int j = 0; j < 4; j++)
#pragma unroll
            for (int q = 0; q < 4; q++) acc[i][j][q] = 0.f;

    load_tiles(0, 0);
    load_tiles(1, 1);
    for (int kt = 0; kt < KT2; kt++) {
        if (kt + 1 < KT2) cp_wait<1>(); else cp_wait<0>();
        __syncthreads();
        if (kt + 2 < KT2) load_tiles(kt + 2, (kt + 2) % STAGES);
        uint32_t sa = sm + (kt % STAGES) * STAGE_BYTES;
        uint32_t sb = sa + A_BYTES;
#pragma unroll
        for (int ks = 0; ks < 2; ks++) {
            uint32_t af[4][4], bf[2][4];
#pragma unroll
            for (int i = 0; i < 4; i++)
                ldsm_x4(af[i], sa + a_loff + (wm * 64 + i * 16) * ASTRIDE + ks * 32);
#pragma unroll
            for (int j = 0; j < 2; j++)
                ldsm_x4_t(bf[j], sb + b_loff + ks * 16 * BSTRIDE + (wn * 32 + j * 16) * 2);
#pragma unroll
            for (int i = 0; i < 4; i++) {
                mma_f16(acc[i][0], af[i], bf[0][0], bf[0][1]);
                mma_f16(acc[i][1], af[i], bf[0][2], bf[0][3]);
                mma_f16(acc[i][2], af[i], bf[1][0], bf[1][1]);
                mma_f16(acc[i][3], af[i], bf[1][2], bf[1][3]);
            }
        }
    }

    // epilogue: accumulate partial into d_out (scattered rows), bias on slice 0
    bool addBias = (blockIdx.z == 0);
#pragma unroll
    for (int i = 0; i < 4; i++) {
        int r0 = m_blk + wm * 64 + i * 16 + g;
        int r1 = r0 + 8;
        int o0 = g_perm[r0], o1 = g_perm[r1];
        float* p0r = outGlob + (size_t)o0 * OUT_DIM;
        float* p1r = outGlob + (size_t)o1 * OUT_DIM;
#pragma unroll
        for (int j = 0; j < 4; j++) {
            int c = n_blk + wn * 32 + j * 8 + 2 * t4;
            float bv0 = addBias ? bias[c] : 0.f;
            float bv1 = addBias ? bias[c + 1] : 0.f;
            atomicAdd(p0r + c,     acc[i][j][0] + bv0);
            atomicAdd(p0r + c + 1, acc[i][j][1] + bv1);
            atomicAdd(p1r + c,     acc[i][j][2] + bv0);
            atomicAdd(p1r + c + 1, acc[i][j][3] + bv1);
        }
    }
}

// ---------------- launch ----------------
extern "C" void kernel_launch(void* const* d_in, const int* in_sizes, int n_in,
                              void* d_out, int out_size) {
    const float* x        = (const float*)d_in[0];
    const float* router_w = (const float*)d_in[1];
    const float* router_b = (const float*)d_in[2];
    const float* expert_w = (const float*)d_in[3];
    const float* expert_b = (const float*)d_in[4];
    const float* proj_w   = (const float*)d_in[5];
    const float* proj_b   = (const float*)d_in[6];

    float* out       = (float*)d_out;
    float* route_out = out + (size_t)BATCH * OUT_DIM;   // [out | one_hot]

    // one-time setup on the FIRST (uncaptured correctness) call; reused during capture
    static cudaStream_t s2 = nullptr;
    static cudaEvent_t ev_fork = nullptr, ev_j1 = nullptr, ev_j2 = nullptr;
    if (!s2) {
        cudaStreamCreateWithFlags(&s2, cudaStreamNonBlocking);
        cudaEventCreateWithFlags(&ev_fork, cudaEventDisableTiming);
        cudaEventCreateWithFlags(&ev_j1, cudaEventDisableTiming);
        cudaEventCreateWithFlags(&ev_j2, cudaEventDisableTiming);
        cudaFuncSetAttribute(gemm1_kernel,
                             cudaFuncAttributeMaxDynamicSharedMemorySize, GEMM_SMEM);
        cudaFuncSetAttribute(gemm2_kernel,
                             cudaFuncAttributeMaxDynamicSharedMemorySize, GEMM2_SMEM);
    }

    // fork: side stream does weight conversion + out zeroing, overlapping
    // with router/perm on the main stream.
    cudaEventRecord(ev_fork, 0);
    cudaStreamWaitEvent(s2, ev_fork, 0);
    convert_expert_kernel<<<2048, 256, 0, s2>>>((const float4*)expert_w);
    cudaEventRecord(ev_j1, s2);                      // expert weights ready
    convert_proj_kernel<<<256, 256, 0, s2>>>((const float4*)proj_w);
    zero_out_kernel<<<512, 256, 0, s2>>>((float4*)out);
    cudaEventRecord(ev_j2, s2);                      // proj weights + zeroed out ready

    zero_kernel<<<1, 32>>>();
    router_kernel<<<BATCH / 8, 256>>>(x, router_w, router_b, route_out);
    perm_kernel<<<BATCH / 256, 256>>>();

    cudaStreamWaitEvent(0, ev_j1, 0);
    gemm1_kernel<<<dim3(HID_DIM / BN, BATCH / BM, N_EXP),
                   THREADS, GEMM_SMEM>>>(expert_b);

    cudaStreamWaitEvent(0, ev_j2, 0);
    gemm2_kernel<<<dim3(OUT_DIM / BN, BATCH / BM, KSPLIT),
                   THREADS, GEMM2_SMEM>>>(proj_b, out);
}